// round 2
// baseline (speedup 1.0000x reference)
#include <cuda_runtime.h>
#include <cstdint>

// ---------------- problem constants ----------------
#define BATCH   2048
#define RDIM    256
#define HIDD    256
#define CONDD   128
#define ZCD     384          // HIDD + CONDD
#define NCHD    64
#define MAXLEN  128
#define ROWS    16           // batch rows per block
#define NBLK    (BATCH/ROWS) // 128
#define NT      256          // threads per block
#define K2N     (RDIM/2)     // 128 paired-k steps

// ---------------- device-global scratch (no allocs allowed) ----------------
// Paired (k-even,k-odd) interleaved, column-major-per-k2 layouts so that the
// hot loop does coalesced LDG.64 across threads.
__device__ float2 g_WrzP [K2N * 512];   // combined (W_ih+W_hh) r|z gates, steps>=1
__device__ float2 g_Wrz0P[K2N * 512];   // W_hh-only r|z gates, step 0
__device__ float2 g_WinP [K2N * 256];   // W_ih n-gate
__device__ float2 g_WhnP [K2N * 256];   // W_hh n-gate
__device__ float2 g_WoutP[K2N * NCHD];  // W_out transposed+paired
__device__ float  g_WlhT [ZCD * RDIM];  // W_lh transposed
__device__ float  g_brz  [512];         // b_ih + b_hh for r|z gates

// ---------------- packed dual-fp32 FMA (sm_100+) ----------------
__device__ __forceinline__ float2 ffma2(float2 a, float2 b, float2 c) {
    unsigned long long au = *reinterpret_cast<unsigned long long*>(&a);
    unsigned long long bu = *reinterpret_cast<unsigned long long*>(&b);
    unsigned long long cu = *reinterpret_cast<unsigned long long*>(&c);
    unsigned long long du;
    asm("fma.rn.f32x2 %0, %1, %2, %3;" : "=l"(du) : "l"(au), "l"(bu), "l"(cu));
    return *reinterpret_cast<float2*>(&du);
}

__device__ __forceinline__ float sigf(float x) {
    return 1.0f / (1.0f + __expf(-x));
}

// ---------------- prologue: build transposed / combined weights ----------------
__global__ void prep_kernel(const float* __restrict__ Wih,
                            const float* __restrict__ Whh,
                            const float* __restrict__ bih,
                            const float* __restrict__ bhh,
                            const float* __restrict__ Wout,
                            const float* __restrict__ Wlh) {
    int i0 = blockIdx.x * blockDim.x + threadIdx.x;
    int stride = gridDim.x * blockDim.x;

    for (int idx = i0; idx < K2N * 512; idx += stride) {
        int k2 = idx >> 9;        // /512
        int c  = idx & 511;
        int k0 = 2 * k2;
        float a0 = Wih[c * RDIM + k0],     a1 = Wih[c * RDIM + k0 + 1];
        float b0 = Whh[c * RDIM + k0],     b1 = Whh[c * RDIM + k0 + 1];
        g_WrzP[idx]  = make_float2(a0 + b0, a1 + b1);
        g_Wrz0P[idx] = make_float2(b0, b1);
    }
    for (int idx = i0; idx < K2N * 256; idx += stride) {
        int k2 = idx >> 8;
        int c  = idx & 255;
        int k0 = 2 * k2;
        g_WinP[idx] = make_float2(Wih[(512 + c) * RDIM + k0], Wih[(512 + c) * RDIM + k0 + 1]);
        g_WhnP[idx] = make_float2(Whh[(512 + c) * RDIM + k0], Whh[(512 + c) * RDIM + k0 + 1]);
    }
    for (int idx = i0; idx < K2N * NCHD; idx += stride) {
        int k2 = idx >> 6;
        int o  = idx & 63;
        int k0 = 2 * k2;
        g_WoutP[idx] = make_float2(Wout[o * RDIM + k0], Wout[o * RDIM + k0 + 1]);
    }
    for (int idx = i0; idx < ZCD * RDIM; idx += stride) {
        int k = idx >> 8;   // /256
        int c = idx & 255;
        g_WlhT[idx] = Wlh[c * ZCD + k];
    }
    for (int idx = i0; idx < 512; idx += stride)
        g_brz[idx] = bih[idx] + bhh[idx];
}

// ---------------- main persistent GRU kernel ----------------
// Each block owns ROWS=16 batch rows; h lives in SMEM for all 128 steps.
// Thread tid owns gate columns {r:tid, u:tid+256, i_n:tid, h_n:tid} -> the
// elementwise GRU update needs no inter-thread exchange.
__global__ void __launch_bounds__(NT, 1)
gru_main_kernel(const float* __restrict__ z,
                const float* __restrict__ xc,
                const float* __restrict__ blh,
                const float* __restrict__ bih,
                const float* __restrict__ bhh,
                const float* __restrict__ bout,
                float* __restrict__ out) {
    __shared__ __align__(16) float h_s[ROWS * RDIM];       // 16 KB
    __shared__ __align__(16) float zc_s[ROWS * ZCD];       // 24 KB (used only for h0)

    const int tid  = threadIdx.x;
    const int row0 = blockIdx.x * ROWS;

    // ---- load [z, x_cond] slice ----
    for (int i = tid; i < ROWS * HIDD; i += NT) {
        int r = i / HIDD, c = i % HIDD;
        zc_s[r * ZCD + c] = z[(row0 + r) * HIDD + c];
    }
    for (int i = tid; i < ROWS * CONDD; i += NT) {
        int r = i / CONDD, c = i % CONDD;
        zc_s[r * ZCD + HIDD + c] = xc[(row0 + r) * CONDD + c];
    }
    __syncthreads();

    // ---- h0 = zc @ W_lh^T + b_lh ----
    {
        float acc[ROWS];
        float bv = blh[tid];
        #pragma unroll
        for (int r = 0; r < ROWS; ++r) acc[r] = bv;
        for (int k = 0; k < ZCD; ++k) {
            float w = g_WlhT[k * RDIM + tid];
            #pragma unroll
            for (int r = 0; r < ROWS; ++r)
                acc[r] = fmaf(zc_s[r * ZCD + k], w, acc[r]);
        }
        #pragma unroll
        for (int r = 0; r < ROWS; ++r) h_s[r * RDIM + tid] = acc[r];
    }
    __syncthreads();

    const float2* hs2 = reinterpret_cast<const float2*>(h_s);
    const float b_rz_r = g_brz[tid];
    const float b_rz_u = g_brz[256 + tid];
    const float b_in   = bih[512 + tid];
    const float b_hn   = bhh[512 + tid];
    const int   oc     = tid & 63;
    const int   orow   = (tid >> 6) * 4;
    const float bo     = bout[oc];

    for (int t = 0; t < MAXLEN; ++t) {
        const bool first = (t == 0);
        const float2* __restrict__ Wrz = first ? g_Wrz0P : g_WrzP;

        // ---- phase A: r and u gate pre-activations ----
        float2 aR[ROWS], aU[ROWS];
        #pragma unroll
        for (int r = 0; r < ROWS; ++r) { aR[r] = make_float2(0.f, 0.f); aU[r] = make_float2(0.f, 0.f); }

        #pragma unroll 2
        for (int k2 = 0; k2 < K2N; ++k2) {
            float2 wr = Wrz[k2 * 512 + tid];
            float2 wu = Wrz[k2 * 512 + 256 + tid];
            #pragma unroll
            for (int r = 0; r < ROWS; ++r) {
                float2 hv = hs2[r * K2N + k2];
                aR[r] = ffma2(hv, wr, aR[r]);
                aU[r] = ffma2(hv, wu, aU[r]);
            }
        }
        float rg[ROWS], ug[ROWS];
        #pragma unroll
        for (int r = 0; r < ROWS; ++r) {
            rg[r] = sigf(aR[r].x + aR[r].y + b_rz_r);
            ug[r] = sigf(aU[r].x + aU[r].y + b_rz_u);
        }

        // ---- phase B: i_n (skip at t=0 since x=0) and h_n pre-activations ----
        float2 aN[ROWS], aH[ROWS];
        #pragma unroll
        for (int r = 0; r < ROWS; ++r) { aN[r] = make_float2(0.f, 0.f); aH[r] = make_float2(0.f, 0.f); }

        if (first) {
            #pragma unroll 2
            for (int k2 = 0; k2 < K2N; ++k2) {
                float2 wh = g_WhnP[k2 * 256 + tid];
                #pragma unroll
                for (int r = 0; r < ROWS; ++r) {
                    float2 hv = hs2[r * K2N + k2];
                    aH[r] = ffma2(hv, wh, aH[r]);
                }
            }
        } else {
            #pragma unroll 2
            for (int k2 = 0; k2 < K2N; ++k2) {
                float2 wn = g_WinP[k2 * 256 + tid];
                float2 wh = g_WhnP[k2 * 256 + tid];
                #pragma unroll
                for (int r = 0; r < ROWS; ++r) {
                    float2 hv = hs2[r * K2N + k2];
                    aN[r] = ffma2(hv, wn, aN[r]);
                    aH[r] = ffma2(hv, wh, aH[r]);
                }
            }
        }

        // ---- elementwise GRU update (column tid, all 16 rows) ----
        float hnew[ROWS];
        #pragma unroll
        for (int r = 0; r < ROWS; ++r) {
            float i_n = aN[r].x + aN[r].y + b_in;     // == b_in at t=0
            float h_n = aH[r].x + aH[r].y + b_hn;
            float nn  = tanhf(fmaf(rg[r], h_n, i_n));
            float ho  = h_s[r * RDIM + tid];
            hnew[r]   = fmaf(ug[r], ho - nn, nn);     // (1-u)*n + u*h
        }
        __syncthreads();   // everyone done reading old h
        #pragma unroll
        for (int r = 0; r < ROWS; ++r) h_s[r * RDIM + tid] = hnew[r];
        __syncthreads();   // new h published

        // ---- logits = h_new @ W_out^T + b_out ----
        {
            float2 lacc[4];
            #pragma unroll
            for (int j = 0; j < 4; ++j) lacc[j] = make_float2(0.f, 0.f);
            #pragma unroll 2
            for (int k2 = 0; k2 < K2N; ++k2) {
                float2 wo = g_WoutP[k2 * NCHD + oc];
                #pragma unroll
                for (int j = 0; j < 4; ++j) {
                    float2 hv = hs2[(orow + j) * K2N + k2];
                    lacc[j] = ffma2(hv, wo, lacc[j]);
                }
            }
            #pragma unroll
            for (int j = 0; j < 4; ++j) {
                int grow = row0 + orow + j;
                out[(grow * MAXLEN + t) * NCHD + oc] = lacc[j].x + lacc[j].y + bo;
            }
        }
    }
}

// ---------------- launcher ----------------
extern "C" void kernel_launch(void* const* d_in, const int* in_sizes, int n_in,
                              void* d_out, int out_size) {
    const float* z     = (const float*)d_in[0];   // (2048, 256)
    const float* xcond = (const float*)d_in[1];   // (2048, 128)
    const float* W_lh  = (const float*)d_in[2];   // (256, 384)
    const float* b_lh  = (const float*)d_in[3];   // (256,)
    const float* W_ih  = (const float*)d_in[4];   // (768, 256)
    const float* W_hh  = (const float*)d_in[5];   // (768, 256)
    const float* b_ih  = (const float*)d_in[6];   // (768,)
    const float* b_hh  = (const float*)d_in[7];   // (768,)
    const float* W_out = (const float*)d_in[8];   // (64, 256)
    const float* b_out = (const float*)d_in[9];   // (64,)
    float* out = (float*)d_out;                   // (2048, 128, 64)

    prep_kernel<<<128, 256>>>(W_ih, W_hh, b_ih, b_hh, W_out, W_lh);
    gru_main_kernel<<<NBLK, NT>>>(z, xcond, b_lh, b_ih, b_hh, b_out, out);
}

// round 3
// speedup vs baseline: 1.1092x; 1.1092x over previous
#include <cuda_runtime.h>
#include <cstdint>

// ---------------- problem constants ----------------
#define BATCH   2048
#define RDIM    256
#define HIDD    256
#define CONDD   128
#define ZCD     384          // HIDD + CONDD
#define NCHD    64
#define MAXLEN  128
#define ROWS    16           // batch rows per block
#define NBLK    (BATCH/ROWS) // 128
#define NT      256          // threads per block
#define K4N     (RDIM/4)     // 64 quad-k steps

// ---------------- device-global scratch (no allocs allowed) ----------------
// k-quad (float4 over k) layouts, column-indexed so the hot loop does
// coalesced LDG.128 across threads.
// g_WrzQ[k4*512 + c]: combined (Wih+Whh) row c (r gates: c<256, u gates: c>=256)
// g_WnQ [k4*512 + c]: c<256 -> Wih[512+c] (i_n), c>=256 -> Whh[256+c] (h_n)
__device__ float4 g_WrzQ [K4N * 512];
__device__ float4 g_WrzQ0[K4N * 512];   // t=0 variant: Whh only (x==0)
__device__ float4 g_WnQ  [K4N * 512];
__device__ float4 g_WnQ0 [K4N * 512];   // t=0 variant: i_n part zeroed
__device__ float4 g_WoutQ[K4N * NCHD];
__device__ float  g_WlhT [ZCD * RDIM];
__device__ float  g_brz  [512];         // b_ih + b_hh for r|u gates

// ---------------- packed dual-fp32 FMA (sm_100+) ----------------
__device__ __forceinline__ float2 ffma2(float2 a, float2 b, float2 c) {
    unsigned long long au = *reinterpret_cast<unsigned long long*>(&a);
    unsigned long long bu = *reinterpret_cast<unsigned long long*>(&b);
    unsigned long long cu = *reinterpret_cast<unsigned long long*>(&c);
    unsigned long long du;
    asm("fma.rn.f32x2 %0, %1, %2, %3;" : "=l"(du) : "l"(au), "l"(bu), "l"(cu));
    return *reinterpret_cast<float2*>(&du);
}
__device__ __forceinline__ float2 lo2(float4 v) { return make_float2(v.x, v.y); }
__device__ __forceinline__ float2 hi2(float4 v) { return make_float2(v.z, v.w); }

__device__ __forceinline__ float sigf(float x) {
    return 1.0f / (1.0f + __expf(-x));
}
__device__ __forceinline__ float tanh_fast(float x) {
    float y;
    asm("tanh.approx.f32 %0, %1;" : "=f"(y) : "f"(x));
    return y;
}

// ---------------- prologue: build transposed / combined weights ----------------
__global__ void prep_kernel(const float* __restrict__ Wih,
                            const float* __restrict__ Whh,
                            const float* __restrict__ bih,
                            const float* __restrict__ bhh,
                            const float* __restrict__ Wout,
                            const float* __restrict__ Wlh) {
    int i0 = blockIdx.x * blockDim.x + threadIdx.x;
    int stride = gridDim.x * blockDim.x;

    for (int idx = i0; idx < K4N * 512; idx += stride) {
        int k4 = idx >> 9;          // /512
        int c  = idx & 511;
        int k0 = 4 * k4;
        // r|u gates: gate row == c (r rows 0..255 of Wih/Whh, u rows 256..511)
        float4 wi = make_float4(Wih[c * RDIM + k0],     Wih[c * RDIM + k0 + 1],
                                Wih[c * RDIM + k0 + 2], Wih[c * RDIM + k0 + 3]);
        float4 wh = make_float4(Whh[c * RDIM + k0],     Whh[c * RDIM + k0 + 1],
                                Whh[c * RDIM + k0 + 2], Whh[c * RDIM + k0 + 3]);
        g_WrzQ[idx]  = make_float4(wi.x + wh.x, wi.y + wh.y, wi.z + wh.z, wi.w + wh.w);
        g_WrzQ0[idx] = wh;

        // n gates: c<256 -> i_n weights (Wih row 512+c); c>=256 -> h_n (Whh row 256+c)
        if (c < 256) {
            int row = 512 + c;
            g_WnQ[idx]  = make_float4(Wih[row * RDIM + k0],     Wih[row * RDIM + k0 + 1],
                                      Wih[row * RDIM + k0 + 2], Wih[row * RDIM + k0 + 3]);
            g_WnQ0[idx] = make_float4(0.f, 0.f, 0.f, 0.f);
        } else {
            int row = 256 + c;   // 512 + (c-256)
            float4 w = make_float4(Whh[row * RDIM + k0],     Whh[row * RDIM + k0 + 1],
                                   Whh[row * RDIM + k0 + 2], Whh[row * RDIM + k0 + 3]);
            g_WnQ[idx]  = w;
            g_WnQ0[idx] = w;
        }
    }
    for (int idx = i0; idx < K4N * NCHD; idx += stride) {
        int k4 = idx >> 6;
        int o  = idx & 63;
        int k0 = 4 * k4;
        g_WoutQ[idx] = make_float4(Wout[o * RDIM + k0],     Wout[o * RDIM + k0 + 1],
                                   Wout[o * RDIM + k0 + 2], Wout[o * RDIM + k0 + 3]);
    }
    for (int idx = i0; idx < ZCD * RDIM; idx += stride) {
        int k = idx >> 8;   // /256
        int c = idx & 255;
        g_WlhT[idx] = Wlh[c * ZCD + k];
    }
    for (int idx = i0; idx < 512; idx += stride)
        g_brz[idx] = bih[idx] + bhh[idx];
}

// ---------------- main persistent GRU kernel ----------------
// One block per SM (128 blocks), 16 batch rows per block, h lives in SMEM for
// all 128 steps. Thread tid owns gate columns {r,u,i_n,h_n} at index tid ->
// elementwise GRU update needs no inter-thread exchange. All four gate
// accumulations are fused into ONE k-loop so each h broadcast is loaded once.
__global__ void __launch_bounds__(NT)
gru_main_kernel(const float* __restrict__ z,
                const float* __restrict__ xc,
                const float* __restrict__ blh,
                const float* __restrict__ bih,
                const float* __restrict__ bhh,
                const float* __restrict__ bout,
                float* __restrict__ out) {
    __shared__ __align__(16) float h_s[ROWS * RDIM];       // 16 KB
    __shared__ __align__(16) float zc_s[ROWS * ZCD];       // 24 KB (init only)

    const int tid  = threadIdx.x;
    const int row0 = blockIdx.x * ROWS;

    // ---- load [z, x_cond] slice ----
    for (int i = tid; i < ROWS * HIDD; i += NT) {
        int r = i / HIDD, c = i % HIDD;
        zc_s[r * ZCD + c] = z[(row0 + r) * HIDD + c];
    }
    for (int i = tid; i < ROWS * CONDD; i += NT) {
        int r = i / CONDD, c = i % CONDD;
        zc_s[r * ZCD + HIDD + c] = xc[(row0 + r) * CONDD + c];
    }
    __syncthreads();

    // ---- h0 = zc @ W_lh^T + b_lh ----
    {
        float acc[ROWS];
        float bv = blh[tid];
        #pragma unroll
        for (int r = 0; r < ROWS; ++r) acc[r] = bv;
        for (int k = 0; k < ZCD; ++k) {
            float w = g_WlhT[k * RDIM + tid];
            #pragma unroll
            for (int r = 0; r < ROWS; ++r)
                acc[r] = fmaf(zc_s[r * ZCD + k], w, acc[r]);
        }
        #pragma unroll
        for (int r = 0; r < ROWS; ++r) h_s[r * RDIM + tid] = acc[r];
    }
    __syncthreads();

    const float4* hs4 = reinterpret_cast<const float4*>(h_s);
    const float b_rz_r = g_brz[tid];
    const float b_rz_u = g_brz[256 + tid];
    const float b_in   = bih[512 + tid];
    const float b_hn   = bhh[512 + tid];
    const int   oc     = tid & 63;
    const int   orow   = (tid >> 6) * 4;
    const float bo     = bout[oc];

    for (int t = 0; t < MAXLEN; ++t) {
        const float4* __restrict__ Wg = (t == 0) ? g_WrzQ0 : g_WrzQ;
        const float4* __restrict__ Wn = (t == 0) ? g_WnQ0  : g_WnQ;

        // ---- fused gate pre-activations: r, u, i_n, h_n in one pass over k ----
        float2 aR[ROWS], aU[ROWS], aN[ROWS], aH[ROWS];
        #pragma unroll
        for (int r = 0; r < ROWS; ++r) {
            aR[r] = make_float2(0.f, 0.f); aU[r] = make_float2(0.f, 0.f);
            aN[r] = make_float2(0.f, 0.f); aH[r] = make_float2(0.f, 0.f);
        }

        #pragma unroll 1
        for (int k4 = 0; k4 < K4N; ++k4) {
            float4 wr = Wg[k4 * 512 + tid];
            float4 wu = Wg[k4 * 512 + 256 + tid];
            float4 wn = Wn[k4 * 512 + tid];
            float4 wh = Wn[k4 * 512 + 256 + tid];
            #pragma unroll
            for (int r = 0; r < ROWS; ++r) {
                float4 hv = hs4[r * K4N + k4];
                float2 hlo = lo2(hv), hhi = hi2(hv);
                aR[r] = ffma2(hlo, lo2(wr), aR[r]);
                aR[r] = ffma2(hhi, hi2(wr), aR[r]);
                aU[r] = ffma2(hlo, lo2(wu), aU[r]);
                aU[r] = ffma2(hhi, hi2(wu), aU[r]);
                aN[r] = ffma2(hlo, lo2(wn), aN[r]);
                aN[r] = ffma2(hhi, hi2(wn), aN[r]);
                aH[r] = ffma2(hlo, lo2(wh), aH[r]);
                aH[r] = ffma2(hhi, hi2(wh), aH[r]);
            }
        }

        // ---- elementwise GRU update (column tid, all 16 rows) ----
        float hnew[ROWS];
        #pragma unroll
        for (int r = 0; r < ROWS; ++r) {
            float rg  = sigf(aR[r].x + aR[r].y + b_rz_r);
            float ug  = sigf(aU[r].x + aU[r].y + b_rz_u);
            float i_n = aN[r].x + aN[r].y + b_in;      // == b_in at t=0
            float h_n = aH[r].x + aH[r].y + b_hn;
            float nn  = tanh_fast(fmaf(rg, h_n, i_n));
            float ho  = h_s[r * RDIM + tid];
            hnew[r]   = fmaf(ug, ho - nn, nn);         // (1-u)*n + u*h
        }
        __syncthreads();   // everyone done reading old h
        #pragma unroll
        for (int r = 0; r < ROWS; ++r) h_s[r * RDIM + tid] = hnew[r];
        __syncthreads();   // new h published

        // ---- logits = h_new @ W_out^T + b_out ----
        {
            float2 lacc[4];
            #pragma unroll
            for (int j = 0; j < 4; ++j) lacc[j] = make_float2(0.f, 0.f);
            #pragma unroll 2
            for (int k4 = 0; k4 < K4N; ++k4) {
                float4 wo = g_WoutQ[k4 * NCHD + oc];
                #pragma unroll
                for (int j = 0; j < 4; ++j) {
                    float4 hv = hs4[(orow + j) * K4N + k4];
                    lacc[j] = ffma2(lo2(hv), lo2(wo), lacc[j]);
                    lacc[j] = ffma2(hi2(hv), hi2(wo), lacc[j]);
                }
            }
            #pragma unroll
            for (int j = 0; j < 4; ++j) {
                int grow = row0 + orow + j;
                out[(grow * MAXLEN + t) * NCHD + oc] = lacc[j].x + lacc[j].y + bo;
            }
        }
    }
}

// ---------------- launcher ----------------
extern "C" void kernel_launch(void* const* d_in, const int* in_sizes, int n_in,
                              void* d_out, int out_size) {
    const float* z     = (const float*)d_in[0];   // (2048, 256)
    const float* xcond = (const float*)d_in[1];   // (2048, 128)
    const float* W_lh  = (const float*)d_in[2];   // (256, 384)
    const float* b_lh  = (const float*)d_in[3];   // (256,)
    const float* W_ih  = (const float*)d_in[4];   // (768, 256)
    const float* W_hh  = (const float*)d_in[5];   // (768, 256)
    const float* b_ih  = (const float*)d_in[6];   // (768,)
    const float* b_hh  = (const float*)d_in[7];   // (768,)
    const float* W_out = (const float*)d_in[8];   // (64, 256)
    const float* b_out = (const float*)d_in[9];   // (64,)
    float* out = (float*)d_out;                   // (2048, 128, 64)

    prep_kernel<<<128, 256>>>(W_ih, W_hh, b_ih, b_hh, W_out, W_lh);
    gru_main_kernel<<<NBLK, NT>>>(z, xcond, b_lh, b_ih, b_hh, b_out, out);
}

// round 4
// speedup vs baseline: 1.4482x; 1.3057x over previous
#include <cuda_runtime.h>
#include <cstdint>

// ---------------- problem constants ----------------
#define BATCH   2048
#define RDIM    256
#define HIDD    256
#define CONDD   128
#define ZCD     384
#define NCHD    64
#define MAXLEN  128
#define ROWS    16
#define NBLK    (BATCH/ROWS)   // 128
#define NT      256
#define K4N     (RDIM/4)       // 64

// streaming geometry
#define CHUNK_K4      4                       // k4-slices per chunk
#define SLICES        (K4N/CHUNK_K4)          // 16 chunks per step
#define CHUNK_F4      (CHUNK_K4 * 1024)       // 4096 float4 = 64KB
#define CHUNK_BYTES   (CHUNK_F4 * 16)         // 65536
#define TOTAL_CHUNKS  (MAXLEN * SLICES)       // 2048

// dynamic smem layout (bytes)
#define SM_H      0                            // float[16*256]   = 16KB
#define SM_WOUT   (16*1024)                    // float4[4096]    = 64KB
#define SM_WBUF   (80*1024)                    // float4[2*4096]  = 128KB
#define SM_MBAR   (208*1024)                   // 2 x u64
#define SM_TOTAL  (208*1024 + 32)

// ---------------- device-global weight streams ----------------
// Per-step weight stream, chunk-major: chunk s holds k4 in [4s,4s+4).
// Within a chunk: [j=0..3][col 0..1023] float4(k..k+3), where
//   col [0,512):   combined Wih[col]+Whh[col]   (r gates 0..255, u gates 256..511)
//   col [512,768): Wih[col]                      (i_n)
//   col [768,1024):Whh[col-256]                  (h_n)
__device__ float4 g_stream [SLICES * CHUNK_F4];   // t >= 1 (1MB)
__device__ float4 g_stream0[SLICES * CHUNK_F4];   // t == 0 (x = 0)
__device__ float4 g_WoutQ[K4N * NCHD];            // 64KB
__device__ float  g_WlhT [ZCD * RDIM];
__device__ float  g_brz  [512];

// ---------------- packed dual-fp32 FMA (sm_100+) ----------------
__device__ __forceinline__ float2 ffma2(float2 a, float2 b, float2 c) {
    unsigned long long au = *reinterpret_cast<unsigned long long*>(&a);
    unsigned long long bu = *reinterpret_cast<unsigned long long*>(&b);
    unsigned long long cu = *reinterpret_cast<unsigned long long*>(&c);
    unsigned long long du;
    asm("fma.rn.f32x2 %0, %1, %2, %3;" : "=l"(du) : "l"(au), "l"(bu), "l"(cu));
    return *reinterpret_cast<float2*>(&du);
}
__device__ __forceinline__ float2 lo2(float4 v) { return make_float2(v.x, v.y); }
__device__ __forceinline__ float2 hi2(float4 v) { return make_float2(v.z, v.w); }
__device__ __forceinline__ float sigf(float x) { return 1.0f / (1.0f + __expf(-x)); }
__device__ __forceinline__ float tanh_fast(float x) {
    float y; asm("tanh.approx.f32 %0, %1;" : "=f"(y) : "f"(x)); return y;
}

// ---------------- mbarrier / bulk-copy helpers ----------------
__device__ __forceinline__ uint32_t smem_u32(const void* p) {
    uint32_t a;
    asm("{ .reg .u64 t; cvta.to.shared.u64 t, %1; cvt.u32.u64 %0, t; }" : "=r"(a) : "l"(p));
    return a;
}
__device__ __forceinline__ void mbar_init(uint32_t m, uint32_t cnt) {
    asm volatile("mbarrier.init.shared.b64 [%0], %1;" :: "r"(m), "r"(cnt) : "memory");
}
__device__ __forceinline__ void mbar_expect_tx(uint32_t m, uint32_t bytes) {
    asm volatile("mbarrier.arrive.expect_tx.shared.b64 _, [%0], %1;" :: "r"(m), "r"(bytes) : "memory");
}
__device__ __forceinline__ void mbar_wait(uint32_t m, uint32_t parity) {
    asm volatile(
        "{\n\t.reg .pred P;\n\t"
        "W:\n\t"
        "mbarrier.try_wait.parity.acquire.cta.shared::cta.b64 P, [%0], %1, 0x989680;\n\t"
        "@P bra D;\n\t"
        "bra W;\n\t"
        "D:\n\t}"
        :: "r"(m), "r"(parity) : "memory");
}
__device__ __forceinline__ void bulk_g2s(uint32_t dst, const void* src, uint32_t bytes, uint32_t mbar) {
    asm volatile("cp.async.bulk.shared::cluster.global.mbarrier::complete_tx::bytes [%0], [%1], %2, [%3];"
                 :: "r"(dst), "l"(src), "r"(bytes), "r"(mbar) : "memory");
}
__device__ __forceinline__ void fence_proxy_async_cta() {
    asm volatile("fence.proxy.async.shared::cta;" ::: "memory");
}

// ---------------- prologue: build streams ----------------
__global__ void prep_kernel(const float* __restrict__ Wih,
                            const float* __restrict__ Whh,
                            const float* __restrict__ bih,
                            const float* __restrict__ bhh,
                            const float* __restrict__ Wout,
                            const float* __restrict__ Wlh) {
    int i0 = blockIdx.x * blockDim.x + threadIdx.x;
    int stride = gridDim.x * blockDim.x;

    for (int idx = i0; idx < K4N * 1024; idx += stride) {
        int k4  = idx >> 10;
        int col = idx & 1023;
        int k0  = 4 * k4;
        int dst = (k4 >> 2) * CHUNK_F4 + (k4 & 3) * 1024 + col;
        float4 w, w0;
        if (col < 512) {
            float4 wi = make_float4(Wih[col*RDIM+k0], Wih[col*RDIM+k0+1], Wih[col*RDIM+k0+2], Wih[col*RDIM+k0+3]);
            float4 wh = make_float4(Whh[col*RDIM+k0], Whh[col*RDIM+k0+1], Whh[col*RDIM+k0+2], Whh[col*RDIM+k0+3]);
            w  = make_float4(wi.x+wh.x, wi.y+wh.y, wi.z+wh.z, wi.w+wh.w);
            w0 = wh;
        } else if (col < 768) {
            int row = col;   // 512..767 -> i_n rows of Wih
            w  = make_float4(Wih[row*RDIM+k0], Wih[row*RDIM+k0+1], Wih[row*RDIM+k0+2], Wih[row*RDIM+k0+3]);
            w0 = make_float4(0.f, 0.f, 0.f, 0.f);
        } else {
            int row = col - 256;   // 512..767 -> h_n rows of Whh
            w  = make_float4(Whh[row*RDIM+k0], Whh[row*RDIM+k0+1], Whh[row*RDIM+k0+2], Whh[row*RDIM+k0+3]);
            w0 = w;
        }
        g_stream[dst]  = w;
        g_stream0[dst] = w0;
    }
    for (int idx = i0; idx < K4N * NCHD; idx += stride) {
        int k4 = idx >> 6;
        int o  = idx & 63;
        int k0 = 4 * k4;
        g_WoutQ[idx] = make_float4(Wout[o*RDIM+k0], Wout[o*RDIM+k0+1], Wout[o*RDIM+k0+2], Wout[o*RDIM+k0+3]);
    }
    for (int idx = i0; idx < ZCD * RDIM; idx += stride) {
        int k = idx >> 8;
        int c = idx & 255;
        g_WlhT[idx] = Wlh[c * ZCD + k];
    }
    for (int idx = i0; idx < 512; idx += stride)
        g_brz[idx] = bih[idx] + bhh[idx];
}

// ---------------- main persistent GRU kernel ----------------
__global__ void __launch_bounds__(NT, 1)
gru_main_kernel(const float* __restrict__ z,
                const float* __restrict__ xc,
                const float* __restrict__ blh,
                const float* __restrict__ bih,
                const float* __restrict__ bhh,
                const float* __restrict__ bout,
                float* __restrict__ out) {
    extern __shared__ __align__(16) char smem[];
    float*        h_s    = reinterpret_cast<float*>(smem + SM_H);
    float4*       wout_s = reinterpret_cast<float4*>(smem + SM_WOUT);
    float4*       wbuf   = reinterpret_cast<float4*>(smem + SM_WBUF);
    uint32_t      mbar0  = smem_u32(smem + SM_MBAR);
    uint32_t      mbar1  = mbar0 + 8;

    const int tid  = threadIdx.x;
    const int row0 = blockIdx.x * ROWS;

    if (tid == 0) { mbar_init(mbar0, 1); mbar_init(mbar1, 1); }

    // ---- stage [z, x_cond] into wbuf area (free pre-stream) ----
    float* zc_s = reinterpret_cast<float*>(wbuf);
    for (int i = tid; i < ROWS * HIDD; i += NT) {
        int r = i / HIDD, c = i % HIDD;
        zc_s[r * ZCD + c] = z[(row0 + r) * HIDD + c];
    }
    for (int i = tid; i < ROWS * CONDD; i += NT) {
        int r = i / CONDD, c = i % CONDD;
        zc_s[r * ZCD + HIDD + c] = xc[(row0 + r) * CONDD + c];
    }
    // ---- park W_out in smem ----
    for (int i = tid; i < K4N * NCHD; i += NT) wout_s[i] = g_WoutQ[i];
    __syncthreads();

    // ---- h0 = zc @ W_lh^T + b_lh ----
    {
        float acc[ROWS];
        float bv = blh[tid];
        #pragma unroll
        for (int r = 0; r < ROWS; ++r) acc[r] = bv;
        for (int k = 0; k < ZCD; ++k) {
            float w = g_WlhT[k * RDIM + tid];
            #pragma unroll
            for (int r = 0; r < ROWS; ++r)
                acc[r] = fmaf(zc_s[r * ZCD + k], w, acc[r]);
        }
        #pragma unroll
        for (int r = 0; r < ROWS; ++r) h_s[r * RDIM + tid] = acc[r];
    }
    __syncthreads();

    // ---- kick off the weight stream: chunks 0 and 1 ----
    if (tid == 0) {
        fence_proxy_async_cta();
        mbar_expect_tx(mbar0, CHUNK_BYTES);
        bulk_g2s(smem_u32(wbuf), g_stream0, CHUNK_BYTES, mbar0);
        mbar_expect_tx(mbar1, CHUNK_BYTES);
        bulk_g2s(smem_u32(wbuf + CHUNK_F4), g_stream0 + CHUNK_F4, CHUNK_BYTES, mbar1);
    }

    const float4* hs4 = reinterpret_cast<const float4*>(h_s);
    const float b_rz_r = g_brz[tid];
    const float b_rz_u = g_brz[256 + tid];
    const float b_in   = bih[512 + tid];
    const float b_hn   = bhh[512 + tid];
    const int   oc     = tid & 63;
    const int   orow   = (tid >> 6) * 4;
    const float bo     = bout[oc];

    uint32_t ph0 = 0, ph1 = 0;
    int c = 0;   // global chunk counter

    for (int t = 0; t < MAXLEN; ++t) {
        float2 aR[ROWS], aU[ROWS], aN[ROWS], aH[ROWS];
        #pragma unroll
        for (int r = 0; r < ROWS; ++r) {
            aR[r] = make_float2(0.f, 0.f); aU[r] = make_float2(0.f, 0.f);
            aN[r] = make_float2(0.f, 0.f); aH[r] = make_float2(0.f, 0.f);
        }

        #pragma unroll 1
        for (int s = 0; s < SLICES; ++s, ++c) {
            const int buf = c & 1;
            if (buf == 0) { mbar_wait(mbar0, ph0); ph0 ^= 1; }
            else          { mbar_wait(mbar1, ph1); ph1 ^= 1; }
            const float4* __restrict__ ws = wbuf + buf * CHUNK_F4;

            #pragma unroll
            for (int j = 0; j < CHUNK_K4; ++j) {
                float4 wr = ws[j * 1024 + tid];
                float4 wu = ws[j * 1024 + 256 + tid];
                float4 wn = ws[j * 1024 + 512 + tid];
                float4 wh = ws[j * 1024 + 768 + tid];
                const int k4 = s * CHUNK_K4 + j;
                #pragma unroll
                for (int r = 0; r < ROWS; ++r) {
                    float4 hv = hs4[r * K4N + k4];
                    float2 hlo = lo2(hv), hhi = hi2(hv);
                    aR[r] = ffma2(hlo, lo2(wr), aR[r]);
                    aR[r] = ffma2(hhi, hi2(wr), aR[r]);
                    aU[r] = ffma2(hlo, lo2(wu), aU[r]);
                    aU[r] = ffma2(hhi, hi2(wu), aU[r]);
                    aN[r] = ffma2(hlo, lo2(wn), aN[r]);
                    aN[r] = ffma2(hhi, hi2(wn), aN[r]);
                    aH[r] = ffma2(hlo, lo2(wh), aH[r]);
                    aH[r] = ffma2(hhi, hi2(wh), aH[r]);
                }
            }
            __syncthreads();   // all threads done reading this buffer
            if (tid == 0 && c + 2 < TOTAL_CHUNKS) {
                const int cn   = c + 2;
                const int step = cn >> 4;
                const int sl   = cn & 15;
                const float4* src = (step == 0 ? g_stream0 : g_stream) + sl * CHUNK_F4;
                if (buf == 0) { mbar_expect_tx(mbar0, CHUNK_BYTES); bulk_g2s(smem_u32(wbuf), src, CHUNK_BYTES, mbar0); }
                else          { mbar_expect_tx(mbar1, CHUNK_BYTES); bulk_g2s(smem_u32(wbuf + CHUNK_F4), src, CHUNK_BYTES, mbar1); }
            }
        }

        // ---- elementwise GRU update ----
        float hnew[ROWS];
        #pragma unroll
        for (int r = 0; r < ROWS; ++r) {
            float rg  = sigf(aR[r].x + aR[r].y + b_rz_r);
            float ug  = sigf(aU[r].x + aU[r].y + b_rz_u);
            float i_n = aN[r].x + aN[r].y + b_in;
            float h_n = aH[r].x + aH[r].y + b_hn;
            float nn  = tanh_fast(fmaf(rg, h_n, i_n));
            float ho  = h_s[r * RDIM + tid];
            hnew[r]   = fmaf(ug, ho - nn, nn);
        }
        __syncthreads();
        #pragma unroll
        for (int r = 0; r < ROWS; ++r) h_s[r * RDIM + tid] = hnew[r];
        __syncthreads();

        // ---- logits = h_new @ W_out^T + b_out (weights in smem) ----
        {
            float2 lacc[4];
            #pragma unroll
            for (int j = 0; j < 4; ++j) lacc[j] = make_float2(0.f, 0.f);
            #pragma unroll 4
            for (int k4 = 0; k4 < K4N; ++k4) {
                float4 wo = wout_s[k4 * NCHD + oc];
                #pragma unroll
                for (int j = 0; j < 4; ++j) {
                    float4 hv = hs4[(orow + j) * K4N + k4];
                    lacc[j] = ffma2(lo2(hv), lo2(wo), lacc[j]);
                    lacc[j] = ffma2(hi2(hv), hi2(wo), lacc[j]);
                }
            }
            #pragma unroll
            for (int j = 0; j < 4; ++j) {
                int grow = row0 + orow + j;
                out[(grow * MAXLEN + t) * NCHD + oc] = lacc[j].x + lacc[j].y + bo;
            }
        }
    }
}

// ---------------- launcher ----------------
extern "C" void kernel_launch(void* const* d_in, const int* in_sizes, int n_in,
                              void* d_out, int out_size) {
    const float* z     = (const float*)d_in[0];
    const float* xcond = (const float*)d_in[1];
    const float* W_lh  = (const float*)d_in[2];
    const float* b_lh  = (const float*)d_in[3];
    const float* W_ih  = (const float*)d_in[4];
    const float* W_hh  = (const float*)d_in[5];
    const float* b_ih  = (const float*)d_in[6];
    const float* b_hh  = (const float*)d_in[7];
    const float* W_out = (const float*)d_in[8];
    const float* b_out = (const float*)d_in[9];
    float* out = (float*)d_out;

    prep_kernel<<<128, 256>>>(W_ih, W_hh, b_ih, b_hh, W_out, W_lh);

    cudaFuncSetAttribute(gru_main_kernel, cudaFuncAttributeMaxDynamicSharedMemorySize, SM_TOTAL);
    gru_main_kernel<<<NBLK, NT, SM_TOTAL>>>(z, xcond, b_lh, b_ih, b_hh, b_out, out);
}

// round 6
// speedup vs baseline: 2.3250x; 1.6054x over previous
#include <cuda_runtime.h>
#include <cuda_bf16.h>
#include <cstdint>

// ---------------- problem constants ----------------
#define BATCH   2048
#define RDIM    256
#define HIDD    256
#define CONDD   128
#define ZCD     384
#define NCHD    64
#define MAXLEN  128
#define ROWS    16
#define NBLK    (BATCH/ROWS)     // 128 CTAs
#define NT      256              // 8 warps
#define NTOT    136              // total n8-tiles: (1024 gate cols + 64 logit cols)/8
#define NT_W    17               // n-tiles per warp
#define NSTEPS  129              // 128 GRU steps + 1 logits-only pseudo-step
#define TOTCHUNK (NSTEPS*16)
#define CHUNK_U4 (NTOT*32)       // 4352 uint4 per ktile-chunk
#define CHUNK_BYTES (CHUNK_U4*16) // 69632
#define APITCH  264              // bf16 pitch of A (h) buffer: bank-conflict-free
#define SMEM_DYN (2*CHUNK_BYTES) // 139264

// ---------------- device-global scratch ----------------
// B-fragment weight stream: [variant 2][ktile 16][ntile 136][lane 32] of
// uint4 {hiB0, hiB1, loB0, loB1} in mma.m16n8k16 col-major B frag layout.
__device__ __align__(16) uint4 g_bstream[2 * 16 * CHUNK_U4];   // 2.23MB
__device__ float g_WlhT[ZCD * RDIM];

// ---------------- helpers ----------------
__device__ __forceinline__ float sigf(float x) { return 1.0f / (1.0f + __expf(-x)); }
__device__ __forceinline__ float tanha(float x) {
    float y; asm("tanh.approx.f32 %0, %1;" : "=f"(y) : "f"(x)); return y;
}
__device__ __forceinline__ unsigned short bf16_bits(float x) {
    __nv_bfloat16 b = __float2bfloat16(x);
    return *reinterpret_cast<unsigned short*>(&b);
}
__device__ __forceinline__ float bf16_val(float x) {
    __nv_bfloat16 b = __float2bfloat16(x);
    return __bfloat162float(b);
}
__device__ __forceinline__ uint32_t pack_hi2(float a, float b) {
    return (uint32_t)bf16_bits(a) | ((uint32_t)bf16_bits(b) << 16);
}
__device__ __forceinline__ uint32_t pack_lo2(float a, float b) {
    return (uint32_t)bf16_bits(a - bf16_val(a)) | ((uint32_t)bf16_bits(b - bf16_val(b)) << 16);
}
__device__ __forceinline__ uint32_t smem_u32(const void* p) {
    uint32_t a;
    asm("{ .reg .u64 t; cvta.to.shared.u64 t, %1; cvt.u32.u64 %0, t; }" : "=r"(a) : "l"(p));
    return a;
}
__device__ __forceinline__ void mbar_init(uint32_t m, uint32_t cnt) {
    asm volatile("mbarrier.init.shared.b64 [%0], %1;" :: "r"(m), "r"(cnt) : "memory");
}
__device__ __forceinline__ void mbar_expect_tx(uint32_t m, uint32_t bytes) {
    asm volatile("mbarrier.arrive.expect_tx.shared.b64 _, [%0], %1;" :: "r"(m), "r"(bytes) : "memory");
}
__device__ __forceinline__ void mbar_wait(uint32_t m, uint32_t parity) {
    asm volatile(
        "{\n\t.reg .pred P;\n\t"
        "W:\n\t"
        "mbarrier.try_wait.parity.acquire.cta.shared::cta.b64 P, [%0], %1, 0x989680;\n\t"
        "@P bra D;\n\t"
        "bra W;\n\t"
        "D:\n\t}"
        :: "r"(m), "r"(parity) : "memory");
}
__device__ __forceinline__ void bulk_g2s(uint32_t dst, const void* src, uint32_t bytes, uint32_t mbar) {
    asm volatile("cp.async.bulk.shared::cluster.global.mbarrier::complete_tx::bytes [%0], [%1], %2, [%3];"
                 :: "r"(dst), "l"(src), "r"(bytes), "r"(mbar) : "memory");
}
__device__ __forceinline__ void fence_proxy_async_cta() {
    asm volatile("fence.proxy.async.shared::cta;" ::: "memory");
}
// m16n8k16 row.col bf16 -> f32 accumulate (generic PTX, sm_80+)
__device__ __forceinline__ void mma16816(float* d, uint32_t a0, uint32_t a1, uint32_t a2, uint32_t a3,
                                         uint32_t b0, uint32_t b1) {
    asm volatile(
        "mma.sync.aligned.m16n8k16.row.col.f32.bf16.bf16.f32 "
        "{%0,%1,%2,%3}, {%4,%5,%6,%7}, {%8,%9}, {%0,%1,%2,%3};"
        : "+f"(d[0]), "+f"(d[1]), "+f"(d[2]), "+f"(d[3])
        : "r"(a0), "r"(a1), "r"(a2), "r"(a3), "r"(b0), "r"(b1));
}

// ---------------- prep: pack B-fragment weight stream ----------------
__device__ __forceinline__ float wval(int v, int n, int k,
                                      const float* Wih, const float* Whh, const float* Wout) {
    if (n < 1024) {
        int hc = n >> 2, g = n & 3;
        if (g == 0) return v ? (Wih[hc*RDIM+k] + Whh[hc*RDIM+k]) : Whh[hc*RDIM+k];
        if (g == 1) return v ? (Wih[(256+hc)*RDIM+k] + Whh[(256+hc)*RDIM+k]) : Whh[(256+hc)*RDIM+k];
        if (g == 2) return v ? Wih[(512+hc)*RDIM+k] : 0.0f;
        return Whh[(512+hc)*RDIM+k];
    }
    return Wout[(n - 1024)*RDIM + k];
}

__global__ void prep_kernel(const float* __restrict__ Wih,
                            const float* __restrict__ Whh,
                            const float* __restrict__ Wout,
                            const float* __restrict__ Wlh) {
    int i0 = blockIdx.x * blockDim.x + threadIdx.x;
    int stride = gridDim.x * blockDim.x;

    const int TOT = 2 * 16 * CHUNK_U4;
    for (int idx = i0; idx < TOT; idx += stride) {
        int lane = idx & 31;
        int nt   = (idx >> 5) % NTOT;
        int kt   = (idx / (32 * NTOT)) & 15;
        int v    = idx / (32 * NTOT * 16);
        int c    = lane & 3;
        int gq   = lane >> 2;
        int n    = nt * 8 + gq;
        int k0   = kt * 16 + 2 * c;
        float w00 = wval(v, n, k0,     Wih, Whh, Wout);
        float w01 = wval(v, n, k0 + 1, Wih, Whh, Wout);
        float w10 = wval(v, n, k0 + 8, Wih, Whh, Wout);
        float w11 = wval(v, n, k0 + 9, Wih, Whh, Wout);
        uint4 o;
        o.x = pack_hi2(w00, w01);
        o.y = pack_hi2(w10, w11);
        o.z = pack_lo2(w00, w01);
        o.w = pack_lo2(w10, w11);
        g_bstream[idx] = o;
    }
    for (int idx = i0; idx < ZCD * RDIM; idx += stride) {
        int k = idx >> 8, c = idx & 255;
        g_WlhT[idx] = Wlh[c * ZCD + k];
    }
}

// ---------------- main persistent kernel ----------------
__global__ void __launch_bounds__(NT, 1)
gru_main_kernel(const float* __restrict__ z,
                const float* __restrict__ xc,
                const float* __restrict__ blh,
                const float* __restrict__ bih,
                const float* __restrict__ bhh,
                const float* __restrict__ bout,
                float* __restrict__ out) {
    extern __shared__ __align__(16) char dyn_raw[];
    __shared__ __align__(16) float h_s[ROWS * RDIM];                 // fp32 state (exact)
    __shared__ __align__(16) unsigned short ahi_s[ROWS * APITCH];    // bf16 hi of h
    __shared__ __align__(16) unsigned short alo_s[ROWS * APITCH];    // bf16 lo of h
    __shared__ float bias_s[1024];                                   // r|u|in|hn per hcol
    __shared__ float bout_s[NCHD];
    __shared__ __align__(16) unsigned long long mbars[2];

    const int tid  = threadIdx.x;
    const int wid  = tid >> 5;
    const int lane = tid & 31;
    const int row0 = blockIdx.x * ROWS;
    uint32_t mb0 = smem_u32(&mbars[0]);
    uint32_t mb1 = mb0 + 8;
    uint32_t buf0 = smem_u32(dyn_raw);

    if (tid == 0) { mbar_init(mb0, 1); mbar_init(mb1, 1); }
    // biases
    bias_s[tid]       = bih[tid]       + bhh[tid];        // r
    bias_s[256 + tid] = bih[256 + tid] + bhh[256 + tid];  // u
    bias_s[512 + tid] = bih[512 + tid];                   // i_n
    bias_s[768 + tid] = bhh[512 + tid];                   // h_n
    if (tid < NCHD) bout_s[tid] = bout[tid];

    // ---- stage [z, x_cond] into the (not yet used) stream buffer ----
    float* zc_s = reinterpret_cast<float*>(dyn_raw);
    for (int i = tid; i < ROWS * HIDD; i += NT) {
        int r = i / HIDD, c = i % HIDD;
        zc_s[r * ZCD + c] = z[(row0 + r) * HIDD + c];
    }
    for (int i = tid; i < ROWS * CONDD; i += NT) {
        int r = i / CONDD, c = i % CONDD;
        zc_s[r * ZCD + HIDD + c] = xc[(row0 + r) * CONDD + c];
    }
    __syncthreads();

    // ---- h0 = zc @ W_lh^T + b_lh ; write fp32 + bf16 hi/lo ----
    {
        float acc[ROWS];
        float bv = blh[tid];
        #pragma unroll
        for (int r = 0; r < ROWS; ++r) acc[r] = bv;
        for (int k = 0; k < ZCD; ++k) {
            float w = g_WlhT[k * RDIM + tid];
            #pragma unroll
            for (int r = 0; r < ROWS; ++r)
                acc[r] = fmaf(zc_s[r * ZCD + k], w, acc[r]);
        }
        #pragma unroll
        for (int r = 0; r < ROWS; ++r) {
            float hv = acc[r];
            h_s[r * RDIM + tid]     = hv;
            ahi_s[r * APITCH + tid] = bf16_bits(hv);
            alo_s[r * APITCH + tid] = bf16_bits(hv - bf16_val(hv));
        }
    }
    __syncthreads();

    // ---- start the weight stream (chunks 0, 1) ----
    if (tid == 0) {
        fence_proxy_async_cta();
        mbar_expect_tx(mb0, CHUNK_BYTES);
        bulk_g2s(buf0,               g_bstream,            CHUNK_BYTES, mb0);
        mbar_expect_tx(mb1, CHUNK_BYTES);
        bulk_g2s(buf0 + CHUNK_BYTES, g_bstream + CHUNK_U4, CHUNK_BYTES, mb1);
    }

    const int cc  = lane & 3;      // col quad within n8 tile
    const int gID = lane >> 2;     // row group
    uint32_t ph0 = 0, ph1 = 0;
    int cglob = 0;

    float d[NT_W][4];

    #pragma unroll 1
    for (int t = 0; t < NSTEPS; ++t) {
        #pragma unroll
        for (int j = 0; j < NT_W; ++j) { d[j][0] = 0.f; d[j][1] = 0.f; d[j][2] = 0.f; d[j][3] = 0.f; }

        #pragma unroll 1
        for (int kt = 0; kt < 16; ++kt, ++cglob) {
            const int buf = cglob & 1;
            if (buf == 0) { mbar_wait(mb0, ph0); ph0 ^= 1; }
            else          { mbar_wait(mb1, ph1); ph1 ^= 1; }
            const uint4* bp = reinterpret_cast<const uint4*>(dyn_raw + buf * CHUNK_BYTES);

            // A fragments for this ktile (bf16x2 pairs from pitch-264 buffers)
            const int k0 = kt * 16 + 2 * cc;
            uint32_t ah0 = *reinterpret_cast<const uint32_t*>(ahi_s + gID * APITCH + k0);
            uint32_t ah1 = *reinterpret_cast<const uint32_t*>(ahi_s + (gID + 8) * APITCH + k0);
            uint32_t ah2 = *reinterpret_cast<const uint32_t*>(ahi_s + gID * APITCH + k0 + 8);
            uint32_t ah3 = *reinterpret_cast<const uint32_t*>(ahi_s + (gID + 8) * APITCH + k0 + 8);
            uint32_t al0 = *reinterpret_cast<const uint32_t*>(alo_s + gID * APITCH + k0);
            uint32_t al1 = *reinterpret_cast<const uint32_t*>(alo_s + (gID + 8) * APITCH + k0);
            uint32_t al2 = *reinterpret_cast<const uint32_t*>(alo_s + gID * APITCH + k0 + 8);
            uint32_t al3 = *reinterpret_cast<const uint32_t*>(alo_s + (gID + 8) * APITCH + k0 + 8);

            #pragma unroll
            for (int j = 0; j < NT_W; ++j) {
                const int nt = wid * NT_W + j;
                uint4 B = bp[nt * 32 + lane];
                mma16816(d[j], ah0, ah1, ah2, ah3, B.x, B.y);   // Ahi * Bhi
                mma16816(d[j], ah0, ah1, ah2, ah3, B.z, B.w);   // Ahi * Blo
                mma16816(d[j], al0, al1, al2, al3, B.x, B.y);   // Alo * Bhi
            }
            __syncthreads();   // all warps consumed this buffer
            if (tid == 0 && cglob + 2 < TOTCHUNK) {
                const int cn = cglob + 2;
                const int tt = cn >> 4;
                const int kk = cn & 15;
                const int v  = (tt == 0) ? 0 : 1;
                const uint4* src = g_bstream + (size_t)(v * 16 + kk) * CHUNK_U4;
                if (buf == 0) { mbar_expect_tx(mb0, CHUNK_BYTES); bulk_g2s(buf0, src, CHUNK_BYTES, mb0); }
                else          { mbar_expect_tx(mb1, CHUNK_BYTES); bulk_g2s(buf0 + CHUNK_BYTES, src, CHUNK_BYTES, mb1); }
            }
        }

        // ---- epilogue ----
        #pragma unroll
        for (int j = 0; j < NT_W; ++j) {
            const int nt = wid * NT_W + j;
            if (nt < 128) {
                if (t < MAXLEN) {
                    // exchange gate pairs: even c holds (r,u), odd c holds (i_n,h_n)
                    float e0 = __shfl_xor_sync(0xffffffffu, d[j][0], 1);
                    float e1 = __shfl_xor_sync(0xffffffffu, d[j][1], 1);
                    float e2 = __shfl_xor_sync(0xffffffffu, d[j][2], 1);
                    float e3 = __shfl_xor_sync(0xffffffffu, d[j][3], 1);
                    if (!(lane & 1)) {
                        const int hc = nt * 2 + ((lane & 2) >> 1);
                        // row gID
                        {
                            float rr  = sigf(d[j][0] + bias_s[hc]);
                            float uu  = sigf(d[j][1] + bias_s[256 + hc]);
                            float i_n = e0 + bias_s[512 + hc];
                            float h_n = e1 + bias_s[768 + hc];
                            float nn  = tanha(fmaf(rr, h_n, i_n));
                            float ho  = h_s[gID * RDIM + hc];
                            float hv  = fmaf(uu, ho - nn, nn);
                            h_s[gID * RDIM + hc]     = hv;
                            ahi_s[gID * APITCH + hc] = bf16_bits(hv);
                            alo_s[gID * APITCH + hc] = bf16_bits(hv - bf16_val(hv));
                        }
                        // row gID + 8
                        {
                            float rr  = sigf(d[j][2] + bias_s[hc]);
                            float uu  = sigf(d[j][3] + bias_s[256 + hc]);
                            float i_n = e2 + bias_s[512 + hc];
                            float h_n = e3 + bias_s[768 + hc];
                            float nn  = tanha(fmaf(rr, h_n, i_n));
                            float ho  = h_s[(gID + 8) * RDIM + hc];
                            float hv  = fmaf(uu, ho - nn, nn);
                            h_s[(gID + 8) * RDIM + hc]     = hv;
                            ahi_s[(gID + 8) * APITCH + hc] = bf16_bits(hv);
                            alo_s[(gID + 8) * APITCH + hc] = bf16_bits(hv - bf16_val(hv));
                        }
                    }
                }
            } else if (t >= 1) {
                // logits for step (t-1): D computed from h_{t-1}
                const int oc = (nt - 128) * 8 + 2 * cc;
                const size_t b0i = ((size_t)(row0 + gID) * MAXLEN + (t - 1)) * NCHD + oc;
                const size_t b8i = ((size_t)(row0 + gID + 8) * MAXLEN + (t - 1)) * NCHD + oc;
                out[b0i]     = d[j][0] + bout_s[oc];
                out[b0i + 1] = d[j][1] + bout_s[oc + 1];
                out[b8i]     = d[j][2] + bout_s[oc];
                out[b8i + 1] = d[j][3] + bout_s[oc + 1];
            }
        }
        __syncthreads();   // A buffers updated before next step's loads
    }
}

// ---------------- launcher ----------------
extern "C" void kernel_launch(void* const* d_in, const int* in_sizes, int n_in,
                              void* d_out, int out_size) {
    const float* z     = (const float*)d_in[0];
    const float* xcond = (const float*)d_in[1];
    const float* W_lh  = (const float*)d_in[2];
    const float* b_lh  = (const float*)d_in[3];
    const float* W_ih  = (const float*)d_in[4];
    const float* W_hh  = (const float*)d_in[5];
    const float* b_ih  = (const float*)d_in[6];
    const float* b_hh  = (const float*)d_in[7];
    const float* W_out = (const float*)d_in[8];
    const float* b_out = (const float*)d_in[9];
    float* out = (float*)d_out;

    cudaFuncSetAttribute(gru_main_kernel, cudaFuncAttributeMaxDynamicSharedMemorySize, SMEM_DYN);

    prep_kernel<<<256, 256>>>(W_ih, W_hh, W_out, W_lh);
    gru_main_kernel<<<NBLK, NT, SMEM_DYN>>>(z, xcond, b_lh, b_ih, b_hh, b_out, out);
}